// round 8
// baseline (speedup 1.0000x reference)
#include <cuda_runtime.h>
#include <cstdint>

// ---------------------------------------------------------------------------
// Exact integer replication of the reference gate-level fp32 adder circuit.
// Words in IEEE layout: bit31=sign, [30:23]=exp, [22:0]=mant.
// Matches the circuit, NOT IEEE (truncated subnormals, subnormal mantissa path
// takes top 23 bits unshifted, big-diff at ediff>=24, exact cancel -> +0,
// overflow checked on computed_e pre-cancel).
// ---------------------------------------------------------------------------
__device__ __forceinline__ uint32_t fpadd_circuit(uint32_t ua, uint32_t ub) {
    uint32_t sa = ua >> 31, sb = ub >> 31;
    uint32_t ea = (ua >> 23) & 0xFFu, eb = (ub >> 23) & 0xFFu;
    uint32_t ma = ua & 0x7FFFFFu, mb = ub & 0x7FFFFFu;

    uint32_t ha = (ea != 0u) ? 1u : 0u;
    uint32_t hb = (eb != 0u) ? 1u : 0u;
    uint32_t eaf = ha ? ea : 1u;
    uint32_t ebf = hb ? eb : 1u;

    uint32_t Ma = (ha << 27) | (ma << 4);
    uint32_t Mb = (hb << 27) | (mb << 4);
    uint32_t maga = (ha << 23) | ma;
    uint32_t magb = (hb << 23) | mb;

    bool exp_eq = (eaf == ebf);
    bool a_ge_b = (eaf > ebf) || (exp_eq && (maga >= magb));
    bool abs_eq = exp_eq && (maga == magb);

    uint32_t ediff = a_ge_b ? (eaf - ebf) : (ebf - eaf);
    bool big = (ediff >= 24u);

    uint32_t e_max  = a_ge_b ? eaf : ebf;
    uint32_t Ml     = a_ge_b ? Ma  : Mb;
    uint32_t Ms0    = a_ge_b ? Mb  : Ma;

    uint32_t Ms;
    bool shift_sticky;
    if (big) {
        Ms = 0u;
        shift_sticky = (Ms0 != 0u);
    } else {
        Ms = Ms0 >> ediff;
        shift_sticky = (Ms0 & ((1u << ediff) - 1u)) != 0u;
    }

    bool dsign = (sa != sb);
    uint32_t s_large = a_ge_b ? sa : sb;

    uint32_t mant_res, carry;
    if (dsign) {
        mant_res = (Ml - Ms - (shift_sticky ? 1u : 0u)) & 0x0FFFFFFFu;
        carry = 0u;
    } else {
        uint32_t s = Ml + Ms;
        carry = s >> 28;
        mant_res = s & 0x0FFFFFFFu;
    }

    uint32_t lzc = mant_res ? (uint32_t)(__clz(mant_res) - 4) : 28u;
    bool underflow = (lzc >= e_max);
    uint32_t norm = (mant_res << lzc) & 0x0FFFFFFFu;

    uint32_t e_after = (e_max - lzc) & 0xFFu;
    uint32_t e_normal = underflow ? 0u : e_after;
    uint32_t final_e_pre = carry ? ((e_max + 1u) & 0xFFu) : e_normal;

    uint32_t m_pre, r_pre;
    bool st_pre;
    if (carry) {
        m_pre  = mant_res >> 5;
        r_pre  = (mant_res >> 4) & 1u;
        st_pre = (mant_res & 0xFu) != 0u;
    } else {
        m_pre  = (norm >> 4) & 0x7FFFFFu;
        r_pre  = (norm >> 3) & 1u;
        st_pre = (norm & 0x7u) != 0u;
    }
    st_pre = st_pre || shift_sticky;

    uint32_t m_sel = underflow ? (mant_res >> 5) : m_pre;
    bool do_round = (r_pre != 0u) && (st_pre || ((m_sel & 1u) != 0u)) && !underflow;

    uint32_t m24 = m_sel + (do_round ? 1u : 0u);
    uint32_t rc = (m24 >> 23) & 1u;
    uint32_t m_final = m24 & 0x7FFFFFu;
    uint32_t computed_e = (final_e_pre + rc) & 0xFFu;

    bool cancel = dsign && abs_eq;
    uint32_t out_s = cancel ? 0u : s_large;
    uint32_t out_e = cancel ? 0u : computed_e;
    uint32_t out_m = cancel ? 0u : m_final;

    bool ea1 = (ea == 0xFFu), eb1 = (eb == 0xFFu);
    bool manz = (ma != 0u),   mbnz = (mb != 0u);
    bool a_inf = ea1 && !manz, b_inf = eb1 && !mbnz;
    bool any_nan = (ea1 && manz) || (eb1 && mbnz);
    bool res_nan = any_nan || (dsign && a_inf && b_inf);
    bool ovf = (computed_e == 0xFFu);

    uint32_t out = (out_s << 31) | (out_e << 23) | out_m;
    if (a_inf || b_inf || ovf) out = (s_large << 31) | 0x7F800000u;
    if (res_nan)               out = 0x7FFFFFFFu;
    return out;
}

// 4 floats (0.0/1.0 words) -> 4-bit nibble, element0 = MSB of the nibble
__device__ __forceinline__ uint32_t nib4(uint4 v) {
    uint32_t s0 = __byte_perm(v.x, v.y, 0x0073);        // b0=x.b3, b1=y.b3
    uint32_t s1 = __byte_perm(v.z, v.w, 0x0073);
    uint32_t pk = __byte_perm(s0, s1, 0x5410) & 0x01010101u;
    return (pk * 0x08040201u) >> 24;                    // x<<3|y<<2|z<<1|w
}

// One block-swap stage of the 8x8 nibble-matrix transpose held across the
// 8-lane subgroup (p = lane&7).  Nibble slot j of W sits at bits [28-4j..31-4j].
__device__ __forceinline__ uint32_t xpose_stage(uint32_t W, int lane, int d,
                                                uint32_t M1, int sh) {
    uint32_t P = __shfl_xor_sync(0xFFFFFFFFu, W, d);
    uint32_t M0 = ~M1;
    return ((lane & d) == 0) ? ((W & M0) | ((P & M0) >> sh))
                             : ((W & M1) | ((P & M1) << sh));
}

__device__ __forceinline__ uint32_t xpose8(uint32_t W, int lane) {
    W = xpose_stage(W, lane, 1, 0x0F0F0F0Fu, 4);
    W = xpose_stage(W, lane, 2, 0x00FF00FFu, 8);
    W = xpose_stage(W, lane, 4, 0x0000FFFFu, 16);
    return W;
}

__global__ void __launch_bounds__(256)
spike_fp32_adder_kernel(const uint4* __restrict__ A4,
                        const uint4* __restrict__ B4,
                        uint32_t* __restrict__ O,
                        int nrows) {
    const unsigned FULL = 0xFFFFFFFFu;
    const int lane = threadIdx.x & 31;
    const int warp = blockIdx.x * (blockDim.x >> 5) + (threadIdx.x >> 5);
    const int wrow0 = warp << 5;                   // 32 rows per warp
    if (wrow0 >= nrows) return;

    if (wrow0 + 32 <= nrows) {
        // ---- main path: coalesced loads + in-register nibble transpose ----
        const uint4* Af = A4 + (size_t)wrow0 * 8;  // 8 uint4 per row
        const uint4* Bf = B4 + (size_t)wrow0 * 8;
        uint32_t WA = 0u, WB = 0u;
        #pragma unroll
        for (int j = 0; j < 8; ++j) {
            int v = j * 32 + lane;                 // chunk of row 4j+(lane>>3), pos lane&7
            WA |= nib4(Af[v]) << (28 - 4 * j);
            WB |= nib4(Bf[v]) << (28 - 4 * j);
        }
        // after transpose: thread (s=lane>>3, p=lane&7) holds IEEE word of row 4p+s
        uint32_t ua = xpose8(WA, lane);
        uint32_t ub = xpose8(WB, lane);
        uint32_t res = fpadd_circuit(ua, ub);

        // ---- output: shfl gather + coalesced 16B stores ----
        const int sub = lane >> 3;                 // row-within-group-of-4
        const uint32_t e0 = (lane & 7) << 2;       // element offset in row
        #pragma unroll
        for (int k = 0; k < 8; ++k) {
            int idx = (k << 2) + sub;              // row index within warp tile
            uint32_t w = __shfl_sync(FULL, res, 8 * sub + k);  // row 4k+sub holder
            uint4 o;
            o.x = (uint32_t)(((int32_t)(w << (e0 + 0))) >> 31) & 0x3F800000u;
            o.y = (uint32_t)(((int32_t)(w << (e0 + 1))) >> 31) & 0x3F800000u;
            o.z = (uint32_t)(((int32_t)(w << (e0 + 2))) >> 31) & 0x3F800000u;
            o.w = (uint32_t)(((int32_t)(w << (e0 + 3))) >> 31) & 0x3F800000u;
            *(uint4*)(O + (size_t)(wrow0 + idx) * 32 + e0) = o;
        }
    } else {
        // ---- tail path (dead for nrows % 32 == 0): per-thread row ----
        int r = wrow0 + lane;
        if (r < nrows) {
            const uint4* Ar = A4 + (size_t)r * 8;
            const uint4* Br = B4 + (size_t)r * 8;
            uint32_t ua = 0u, ub = 0u;
            #pragma unroll
            for (int k = 0; k < 8; ++k) {
                ua |= nib4(Ar[k]) << (28 - 4 * k);
                ub |= nib4(Br[k]) << (28 - 4 * k);
            }
            uint32_t w = fpadd_circuit(ua, ub);
            #pragma unroll
            for (int k = 0; k < 8; ++k) {
                uint4 o;
                uint32_t e0 = k << 2;
                o.x = (uint32_t)(((int32_t)(w << (e0 + 0))) >> 31) & 0x3F800000u;
                o.y = (uint32_t)(((int32_t)(w << (e0 + 1))) >> 31) & 0x3F800000u;
                o.z = (uint32_t)(((int32_t)(w << (e0 + 2))) >> 31) & 0x3F800000u;
                o.w = (uint32_t)(((int32_t)(w << (e0 + 3))) >> 31) & 0x3F800000u;
                *(uint4*)(O + (size_t)r * 32 + e0) = o;
            }
        }
    }
}

extern "C" void kernel_launch(void* const* d_in, const int* in_sizes, int n_in,
                              void* d_out, int out_size) {
    const uint4* A = (const uint4*)d_in[0];
    const uint4* B = (const uint4*)d_in[1];
    uint32_t* O = (uint32_t*)d_out;

    int nrows  = in_sizes[0] / 32;                 // 524288
    int warps  = (nrows + 31) / 32;                // 16384
    int threads = 256;
    int blocks = (warps + 7) / 8;                  // 2048

    spike_fp32_adder_kernel<<<blocks, threads>>>(A, B, O, nrows);
}